// round 12
// baseline (speedup 1.0000x reference)
#include <cuda_runtime.h>
#include <math.h>

// Problem constants (match reference)
#define B_TOK 8192
#define DIN   1024
#define HID   2048
#define DOUT  1024
#define NEXP  8
#define GHID  1024
#define CAP   8192   // worst-case tokens per expert

// -------- device scratch (static globals; allocation-free) --------
__device__ float g_g1[(size_t)B_TOK * GHID];          //  32 MB  gating hidden
__device__ float g_H  [(size_t)NEXP * CAP * HID];     // 512 MB  relu(x@w1+b1)
__device__ float g_MID[(size_t)NEXP * CAP * HID];     // 512 MB  relu(h@w2 + x@wp + b)
__device__ float g_PO [(size_t)NEXP * CAP * DOUT];    // 256 MB  expert outputs
__device__ int   g_count[NEXP];
__device__ int   g_tok[NEXP * CAP];
__device__ int   g_pairpos[B_TOK * 2];
__device__ float g_pairw [B_TOK * 2];

__device__ __forceinline__ unsigned f2tf(float f) {
    unsigned u;
    asm("cvt.rna.tf32.f32 %0, %1;" : "=r"(u) : "f"(f));
    return u;
}

// =================================================================
// Reset per-expert counters (must run every graph replay)
// =================================================================
__global__ void reset_counts_kernel() {
    if (threadIdx.x < NEXP) g_count[threadIdx.x] = 0;
}

// =================================================================
// Gating epilogue: logits = relu_g1 @ gw2 + gb2 ; top-2 ; softmax ;
// scatter. FP32 throughout — selection must match reference exactly.
// =================================================================
__global__ void gating_topk_scatter_kernel(const float* __restrict__ gw2,
                                           const float* __restrict__ gb2) {
    const int t   = blockIdx.x;
    const int tid = threadIdx.x;

    float acc[NEXP];
#pragma unroll
    for (int e = 0; e < NEXP; e++) acc[e] = 0.f;

    const float* row = g_g1 + (size_t)t * GHID;
    for (int k = tid; k < GHID; k += 128) {
        float v = row[k];
        const float* w = gw2 + (size_t)k * NEXP;
#pragma unroll
        for (int e = 0; e < NEXP; e++) acc[e] += v * w[e];
    }

    __shared__ float sm[128 * NEXP];
#pragma unroll
    for (int e = 0; e < NEXP; e++) sm[tid * NEXP + e] = acc[e];
    __syncthreads();
    for (int s = 64; s > 0; s >>= 1) {
        if (tid < s) {
#pragma unroll
            for (int e = 0; e < NEXP; e++)
                sm[tid * NEXP + e] += sm[(tid + s) * NEXP + e];
        }
        __syncthreads();
    }

    if (tid == 0) {
        float l[NEXP];
#pragma unroll
        for (int e = 0; e < NEXP; e++) l[e] = sm[e] + gb2[e];

        int i0 = 0;
#pragma unroll
        for (int e = 1; e < NEXP; e++) if (l[e] > l[i0]) i0 = e;
        int i1 = -1;
#pragma unroll
        for (int e = 0; e < NEXP; e++) {
            if (e == i0) continue;
            if (i1 < 0 || l[e] > l[i1]) i1 = e;
        }
        float r  = expf(l[i1] - l[i0]);
        float w0 = 1.f / (1.f + r);
        float w1 = r / (1.f + r);

        int p0 = atomicAdd(&g_count[i0], 1);
        int s0 = i0 * CAP + p0;
        g_tok[s0] = t; g_pairpos[2 * t] = s0; g_pairw[2 * t] = w0;

        int p1 = atomicAdd(&g_count[i1], 1);
        int s1 = i1 * CAP + p1;
        g_tok[s1] = t; g_pairpos[2 * t + 1] = s1; g_pairw[2 * t + 1] = w1;
    }
}

// =================================================================
// FP32 gating GEMM (exact): g1 = relu(x @ gw1 + gb1)
// =================================================================
__global__ void __launch_bounds__(256) gating_gemm_kernel(
    const float* __restrict__ x,
    const float* __restrict__ W,
    const float* __restrict__ bias) {

    __shared__ float As[16][128];
    __shared__ float Bs[16][128];

    const int m0 = blockIdx.y * 128;
    const int n0 = blockIdx.x * 128;
    const int tid = threadIdx.x;

    const int ra0 = tid >> 2;
    const int ra1 = 64 + ra0;
    const int kv4 = (tid & 3) * 4;
    const int kb0 = tid >> 5;
    const int kb1 = 8 + kb0;
    const int nv4 = (tid & 31) * 4;

    const float* arow0 = x + (size_t)(m0 + ra0) * DIN;
    const float* arow1 = x + (size_t)(m0 + ra1) * DIN;

    float acc[8][8];
#pragma unroll
    for (int i = 0; i < 8; i++)
#pragma unroll
        for (int j = 0; j < 8; j++) acc[i][j] = 0.f;

    const int ty = tid >> 4;
    const int tx = tid & 15;

    float4 aR0 = *(const float4*)(arow0 + kv4);
    float4 aR1 = *(const float4*)(arow1 + kv4);
    float4 bR0 = *(const float4*)(W + (size_t)kb0 * GHID + n0 + nv4);
    float4 bR1 = *(const float4*)(W + (size_t)kb1 * GHID + n0 + nv4);

    for (int kt = 0; kt < DIN; kt += 16) {
        As[kv4 + 0][ra0] = aR0.x; As[kv4 + 1][ra0] = aR0.y;
        As[kv4 + 2][ra0] = aR0.z; As[kv4 + 3][ra0] = aR0.w;
        As[kv4 + 0][ra1] = aR1.x; As[kv4 + 1][ra1] = aR1.y;
        As[kv4 + 2][ra1] = aR1.z; As[kv4 + 3][ra1] = aR1.w;
        *(float4*)&Bs[kb0][nv4] = bR0;
        *(float4*)&Bs[kb1][nv4] = bR1;
        __syncthreads();

        if (kt + 16 < DIN) {
            aR0 = *(const float4*)(arow0 + kt + 16 + kv4);
            aR1 = *(const float4*)(arow1 + kt + 16 + kv4);
            bR0 = *(const float4*)(W + (size_t)(kt + 16 + kb0) * GHID + n0 + nv4);
            bR1 = *(const float4*)(W + (size_t)(kt + 16 + kb1) * GHID + n0 + nv4);
        }

#pragma unroll
        for (int kk = 0; kk < 16; kk++) {
            float a[8], b[8];
            *(float4*)&a[0] = *(const float4*)&As[kk][4 * ty];
            *(float4*)&a[4] = *(const float4*)&As[kk][64 + 4 * ty];
            *(float4*)&b[0] = *(const float4*)&Bs[kk][4 * tx];
            *(float4*)&b[4] = *(const float4*)&Bs[kk][64 + 4 * tx];
#pragma unroll
            for (int i = 0; i < 8; i++)
#pragma unroll
                for (int j = 0; j < 8; j++) acc[i][j] += a[i] * b[j];
        }
        __syncthreads();
    }

    float bn[8];
    {
        float4 b0 = *(const float4*)&bias[n0 + 4 * tx];
        float4 b1 = *(const float4*)&bias[n0 + 64 + 4 * tx];
        bn[0] = b0.x; bn[1] = b0.y; bn[2] = b0.z; bn[3] = b0.w;
        bn[4] = b1.x; bn[5] = b1.y; bn[6] = b1.z; bn[7] = b1.w;
    }

#pragma unroll
    for (int i = 0; i < 8; i++) {
        int m = m0 + ((i < 4) ? (4 * ty + i) : (64 + 4 * ty + (i - 4)));
        float* crow = g_g1 + (size_t)m * GHID;
        float4 v0, v1;
        v0.x = fmaxf(acc[i][0] + bn[0], 0.f); v0.y = fmaxf(acc[i][1] + bn[1], 0.f);
        v0.z = fmaxf(acc[i][2] + bn[2], 0.f); v0.w = fmaxf(acc[i][3] + bn[3], 0.f);
        v1.x = fmaxf(acc[i][4] + bn[4], 0.f); v1.y = fmaxf(acc[i][5] + bn[5], 0.f);
        v1.z = fmaxf(acc[i][6] + bn[6], 0.f); v1.w = fmaxf(acc[i][7] + bn[7], 0.f);
        *(float4*)&crow[n0 + 4 * tx]      = v0;
        *(float4*)&crow[n0 + 64 + 4 * tx] = v1;
    }
}

// =================================================================
// TF32 mma.sync grouped GEMM. CTA 128x128, BK=16, **4 warps** in a
// 2x2 grid, warp tile 64x64 (4x8 m16n8k8 fragments). Halving warp
// count + doubling warp-N cuts smem fragment traffic from 192 to
// 128 B per MMA (A and B each re-read only 2x). A via ldmatrix.x4,
// double-buffered smem, cvt.rna on the STS path (numerics identical
// to the passing R8 build). 2 CTAs/SM.
// MODE 1: H   = relu(x[tok] @ w1[e] + b1[e])           K=DIN
// MODE 2: MID = relu([H | x[tok]] @ [w2;wp] + b2+bp)   K=HID+DIN
// MODE 3: PO  = MID @ w3[e] + b3[e]                    K=HID
// =================================================================
#define MMA_TF32(d, a, b)                                                    \
    asm volatile(                                                            \
        "mma.sync.aligned.m16n8k8.row.col.f32.tf32.tf32.f32 "                \
        "{%0,%1,%2,%3}, {%4,%5,%6,%7}, {%8,%9}, {%0,%1,%2,%3};\n"            \
        : "+f"((d)[0]), "+f"((d)[1]), "+f"((d)[2]), "+f"((d)[3])             \
        : "r"((a)[0]), "r"((a)[1]), "r"((a)[2]), "r"((a)[3]),                \
          "r"((b)[0]), "r"((b)[1]))

#define LDSM_X4(r, addr)                                                     \
    asm volatile(                                                            \
        "ldmatrix.sync.aligned.m8n8.x4.shared.b16 {%0,%1,%2,%3}, [%4];\n"    \
        : "=r"((r)[0]), "=r"((r)[1]), "=r"((r)[2]), "=r"((r)[3])             \
        : "r"(addr))

#define A_ST 20    // A smem stride (floats)
#define B_ST 136   // B smem stride (floats)

template <int MODE, int KDIM, int NDIM, bool RELU>
__global__ void __launch_bounds__(128, 2) moe_mma_kernel(
    const float* __restrict__ x,
    const float* __restrict__ Wa,
    const float* __restrict__ Wb,
    const float* __restrict__ ba,
    const float* __restrict__ bb) {

    __shared__ unsigned As[2][128 * A_ST];   // [stage][m][k]
    __shared__ unsigned Bs[2][16 * B_ST];    // [stage][k][n]

    const int e = (int)blockIdx.z;
    const int mcount = g_count[e];
    const int m0 = blockIdx.y * 128;
    if (m0 >= mcount) return;
    const int n0 = blockIdx.x * 128;
    const int tid  = threadIdx.x;
    const int lane = tid & 31;
    const int warp = tid >> 5;
    const int wm = (warp & 1) * 64;   // 2 warp-rows
    const int wn = (warp >> 1) * 64;  // 2 warp-cols, 64 wide
    const int group = lane >> 2;
    const int tl    = lane & 3;

    // ---- loader mapping (128 threads) ----
    // A: thread owns tile row tid (16 floats = 4 float4)
    // B: thread owns rows kb+{0,4,8,12}, cols nv4..nv4+3
    const int kb  = tid >> 5;          // 0..3
    const int nv4 = (tid & 31) * 4;

    // expert weight/bias pointers
    const float* W1e = Wa;
    const float* W2e = Wb;
    const float* b1e = ba;
    const float* b2e = bb;
    if (MODE == 1)      { W1e += (size_t)e * DIN * HID;  b1e += (size_t)e * HID; }
    else if (MODE == 2) { W1e += (size_t)e * HID * HID;  W2e += (size_t)e * DIN * HID;
                          b1e += (size_t)e * HID;        b2e += (size_t)e * HID; }
    else                { W1e += (size_t)e * HID * DOUT; b1e += (size_t)e * DOUT; }

    // A row base pointer (rows >= mcount read valid stale slots; never stored)
    const float* arow;
    const float* xrow = x;
    if (MODE == 1) {
        arow = x + (size_t)g_tok[e * CAP + m0 + tid] * DIN;
    } else if (MODE == 2) {
        xrow = x + (size_t)g_tok[e * CAP + m0 + tid] * DIN;
        arow = g_H + (size_t)(e * CAP + m0 + tid) * HID;
    } else {
        arow = g_MID + (size_t)(e * CAP + m0 + tid) * HID;
    }

    float4 aR[4], bR[4];
    auto loadA = [&](int kt) {
        const float* src = (MODE == 2 && kt >= HID) ? (xrow + kt - HID) : (arow + kt);
#pragma unroll
        for (int j = 0; j < 4; j++) aR[j] = *(const float4*)(src + 4 * j);
    };
    auto loadB = [&](int kt) {
        const float* wsrc = W1e;
        int kloc = kt;
        if (MODE == 2 && kt >= HID) { wsrc = W2e; kloc = kt - HID; }
#pragma unroll
        for (int j = 0; j < 4; j++)
            bR[j] = *(const float4*)(wsrc + (size_t)(kloc + kb + 4 * j) * NDIM + n0 + nv4);
    };
    auto store_stage = [&](int s) {
#pragma unroll
        for (int j = 0; j < 4; j++) {
            uint4 u = make_uint4(f2tf(aR[j].x), f2tf(aR[j].y), f2tf(aR[j].z), f2tf(aR[j].w));
            *(uint4*)&As[s][tid * A_ST + 4 * j] = u;
        }
#pragma unroll
        for (int j = 0; j < 4; j++) {
            uint4 u = make_uint4(f2tf(bR[j].x), f2tf(bR[j].y), f2tf(bR[j].z), f2tf(bR[j].w));
            *(uint4*)&Bs[s][(kb + 4 * j) * B_ST + nv4] = u;
        }
    };

    float acc[4][8][4];
#pragma unroll
    for (int mi = 0; mi < 4; mi++)
#pragma unroll
        for (int ni = 0; ni < 8; ni++)
#pragma unroll
            for (int r = 0; r < 4; r++) acc[mi][ni][r] = 0.f;

    loadA(0); loadB(0);
    store_stage(0);
    __syncthreads();

    // LDSM base: row = wm + (lane & 15), k-offset = (lane >> 4) * 4
    const unsigned aLdsmBase = (unsigned)__cvta_generic_to_shared(&As[0][0])
        + (unsigned)(((wm + (lane & 15)) * A_ST + ((lane >> 4) << 2)) * 4);

    const int NCH = KDIM / 16;
#pragma unroll 1
    for (int c = 0; c < NCH; c++) {
        if (c + 1 < NCH) { loadA((c + 1) * 16); loadB((c + 1) * 16); }

        const unsigned aStage = aLdsmBase + (unsigned)((c & 1) * 128 * A_ST * 4);
        const unsigned* Bu = Bs[c & 1];
#pragma unroll
        for (int ks = 0; ks < 16; ks += 8) {
            unsigned a[4][4], b[8][2];
#pragma unroll
            for (int mi = 0; mi < 4; mi++)
                LDSM_X4(a[mi], aStage + (unsigned)((mi * 16 * A_ST + ks) * 4));
#pragma unroll
            for (int ni = 0; ni < 8; ni++) {
                int nb = wn + ni * 8 + group;
                b[ni][0] = Bu[(ks + tl) * B_ST + nb];
                b[ni][1] = Bu[(ks + tl + 4) * B_ST + nb];
            }
#pragma unroll
            for (int mi = 0; mi < 4; mi++)
#pragma unroll
                for (int ni = 0; ni < 8; ni++)
                    MMA_TF32(acc[mi][ni], a[mi], b[ni]);
        }

        if (c + 1 < NCH) store_stage((c + 1) & 1);
        __syncthreads();
    }

    // ---- epilogue: per-column bias, optional relu, fragment store ----
    float2 bn[8];
#pragma unroll
    for (int ni = 0; ni < 8; ni++) {
        int col = n0 + wn + ni * 8 + tl * 2;
        bn[ni] = *(const float2*)&b1e[col];
        if (MODE == 2) {
            float2 c2 = *(const float2*)&b2e[col];
            bn[ni].x += c2.x; bn[ni].y += c2.y;
        }
    }

    float* Cb;
    if (MODE == 1)      Cb = g_H   + (size_t)e * CAP * NDIM;
    else if (MODE == 2) Cb = g_MID + (size_t)e * CAP * NDIM;
    else                Cb = g_PO  + (size_t)e * CAP * NDIM;

#pragma unroll
    for (int mi = 0; mi < 4; mi++) {
        int r0 = m0 + wm + mi * 16 + group;
        int r1 = r0 + 8;
        float* crow0 = Cb + (size_t)r0 * NDIM;
        float* crow1 = Cb + (size_t)r1 * NDIM;
#pragma unroll
        for (int ni = 0; ni < 8; ni++) {
            int col = n0 + wn + ni * 8 + tl * 2;
            float2 v0, v1;
            v0.x = acc[mi][ni][0] + bn[ni].x;
            v0.y = acc[mi][ni][1] + bn[ni].y;
            v1.x = acc[mi][ni][2] + bn[ni].x;
            v1.y = acc[mi][ni][3] + bn[ni].y;
            if (RELU) {
                v0.x = fmaxf(v0.x, 0.f); v0.y = fmaxf(v0.y, 0.f);
                v1.x = fmaxf(v1.x, 0.f); v1.y = fmaxf(v1.y, 0.f);
            }
            if (r0 < mcount) *(float2*)&crow0[col] = v0;
            if (r1 < mcount) *(float2*)&crow1[col] = v1;
        }
    }
}

// =================================================================
// Combine: out[t] = w0 * PO[p0] + w1 * PO[p1]  (deterministic)
// =================================================================
__global__ void combine_kernel(float* __restrict__ out) {
    const int t = blockIdx.x;
    const int p0 = g_pairpos[2 * t], p1 = g_pairpos[2 * t + 1];
    const float w0 = g_pairw[2 * t], w1 = g_pairw[2 * t + 1];
    const float4* r0 = (const float4*)(g_PO + (size_t)p0 * DOUT);
    const float4* r1 = (const float4*)(g_PO + (size_t)p1 * DOUT);
    float4* o = (float4*)(out + (size_t)t * DOUT);
    for (int c = threadIdx.x; c < DOUT / 4; c += blockDim.x) {
        float4 a = r0[c], b = r1[c], v;
        v.x = w0 * a.x + w1 * b.x;
        v.y = w0 * a.y + w1 * b.y;
        v.z = w0 * a.z + w1 * b.z;
        v.w = w0 * a.w + w1 * b.w;
        o[c] = v;
    }
}

// =================================================================
// Launch
// =================================================================
extern "C" void kernel_launch(void* const* d_in, const int* in_sizes, int n_in,
                              void* d_out, int out_size) {
    (void)in_sizes; (void)n_in; (void)out_size;
    const float* x   = (const float*)d_in[0];
    const float* w1  = (const float*)d_in[1];
    const float* b1  = (const float*)d_in[2];
    const float* w2  = (const float*)d_in[3];
    const float* b2  = (const float*)d_in[4];
    const float* w3  = (const float*)d_in[5];
    const float* b3  = (const float*)d_in[6];
    const float* wp  = (const float*)d_in[7];
    const float* bp  = (const float*)d_in[8];
    const float* gw1 = (const float*)d_in[9];
    const float* gb1 = (const float*)d_in[10];
    const float* gw2 = (const float*)d_in[11];
    const float* gb2 = (const float*)d_in[12];
    float* out = (float*)d_out;

    reset_counts_kernel<<<1, 32>>>();

    // Gating GEMM (exact fp32): g1 = relu(x @ gw1 + gb1)
    gating_gemm_kernel<<<dim3(GHID / 128, B_TOK / 128, 1), 256>>>(x, gw1, gb1);

    // Top-2 + softmax + scatter
    gating_topk_scatter_kernel<<<B_TOK, 128>>>(gw2, gb2);

    // GEMM1 (tf32): H = relu(x[tok] @ w1[e] + b1[e])
    moe_mma_kernel<1, DIN, HID, true>
        <<<dim3(HID / 128, CAP / 128, NEXP), 128>>>(x, w1, nullptr, b1, nullptr);

    // GEMM2 (tf32, fused wp): MID = relu([H | x] @ [w2; wp] + b2 + bp)
    moe_mma_kernel<2, HID + DIN, HID, true>
        <<<dim3(HID / 128, CAP / 128, NEXP), 128>>>(x, w2, wp, b2, bp);

    // GEMM3 (tf32): PO = MID @ w3[e] + b3[e]
    moe_mma_kernel<3, HID, DOUT, false>
        <<<dim3(DOUT / 128, CAP / 128, NEXP), 128>>>(x, w3, nullptr, b3, nullptr);

    // Weighted combine into output
    combine_kernel<<<B_TOK, 256>>>(out);
}

// round 13
// speedup vs baseline: 1.1060x; 1.1060x over previous
#include <cuda_runtime.h>
#include <math.h>

// Problem constants (match reference)
#define B_TOK 8192
#define DIN   1024
#define HID   2048
#define DOUT  1024
#define NEXP  8
#define GHID  1024
#define CAP   8192   // worst-case tokens per expert

// -------- device scratch (static globals; allocation-free) --------
__device__ float g_g1[(size_t)B_TOK * GHID];          //  32 MB  gating hidden
__device__ float g_H  [(size_t)NEXP * CAP * HID];     // 512 MB  relu(x@w1+b1)
__device__ float g_MID[(size_t)NEXP * CAP * HID];     // 512 MB  relu(h@w2 + x@wp + b)
__device__ float g_PO [(size_t)NEXP * CAP * DOUT];    // 256 MB  expert outputs
__device__ int   g_count[NEXP];
__device__ int   g_tok[NEXP * CAP];
__device__ int   g_pairpos[B_TOK * 2];
__device__ float g_pairw [B_TOK * 2];

__device__ __forceinline__ unsigned f2tf(float f) {
    unsigned u;
    asm("cvt.rna.tf32.f32 %0, %1;" : "=r"(u) : "f"(f));
    return u;
}

// =================================================================
// Reset per-expert counters (must run every graph replay)
// =================================================================
__global__ void reset_counts_kernel() {
    if (threadIdx.x < NEXP) g_count[threadIdx.x] = 0;
}

// =================================================================
// Gating epilogue: logits = relu_g1 @ gw2 + gb2 ; top-2 ; softmax ;
// scatter. FP32 throughout — selection must match reference exactly.
// =================================================================
__global__ void gating_topk_scatter_kernel(const float* __restrict__ gw2,
                                           const float* __restrict__ gb2) {
    const int t   = blockIdx.x;
    const int tid = threadIdx.x;

    float acc[NEXP];
#pragma unroll
    for (int e = 0; e < NEXP; e++) acc[e] = 0.f;

    const float* row = g_g1 + (size_t)t * GHID;
    for (int k = tid; k < GHID; k += 128) {
        float v = row[k];
        const float* w = gw2 + (size_t)k * NEXP;
#pragma unroll
        for (int e = 0; e < NEXP; e++) acc[e] += v * w[e];
    }

    __shared__ float sm[128 * NEXP];
#pragma unroll
    for (int e = 0; e < NEXP; e++) sm[tid * NEXP + e] = acc[e];
    __syncthreads();
    for (int s = 64; s > 0; s >>= 1) {
        if (tid < s) {
#pragma unroll
            for (int e = 0; e < NEXP; e++)
                sm[tid * NEXP + e] += sm[(tid + s) * NEXP + e];
        }
        __syncthreads();
    }

    if (tid == 0) {
        float l[NEXP];
#pragma unroll
        for (int e = 0; e < NEXP; e++) l[e] = sm[e] + gb2[e];

        int i0 = 0;
#pragma unroll
        for (int e = 1; e < NEXP; e++) if (l[e] > l[i0]) i0 = e;
        int i1 = -1;
#pragma unroll
        for (int e = 0; e < NEXP; e++) {
            if (e == i0) continue;
            if (i1 < 0 || l[e] > l[i1]) i1 = e;
        }
        float r  = expf(l[i1] - l[i0]);
        float w0 = 1.f / (1.f + r);
        float w1 = r / (1.f + r);

        int p0 = atomicAdd(&g_count[i0], 1);
        int s0 = i0 * CAP + p0;
        g_tok[s0] = t; g_pairpos[2 * t] = s0; g_pairw[2 * t] = w0;

        int p1 = atomicAdd(&g_count[i1], 1);
        int s1 = i1 * CAP + p1;
        g_tok[s1] = t; g_pairpos[2 * t + 1] = s1; g_pairw[2 * t + 1] = w1;
    }
}

// =================================================================
// FP32 gating GEMM (exact): g1 = relu(x @ gw1 + gb1)
// =================================================================
__global__ void __launch_bounds__(256) gating_gemm_kernel(
    const float* __restrict__ x,
    const float* __restrict__ W,
    const float* __restrict__ bias) {

    __shared__ float As[16][128];
    __shared__ float Bs[16][128];

    const int m0 = blockIdx.y * 128;
    const int n0 = blockIdx.x * 128;
    const int tid = threadIdx.x;

    const int ra0 = tid >> 2;
    const int ra1 = 64 + ra0;
    const int kv4 = (tid & 3) * 4;
    const int kb0 = tid >> 5;
    const int kb1 = 8 + kb0;
    const int nv4 = (tid & 31) * 4;

    const float* arow0 = x + (size_t)(m0 + ra0) * DIN;
    const float* arow1 = x + (size_t)(m0 + ra1) * DIN;

    float acc[8][8];
#pragma unroll
    for (int i = 0; i < 8; i++)
#pragma unroll
        for (int j = 0; j < 8; j++) acc[i][j] = 0.f;

    const int ty = tid >> 4;
    const int tx = tid & 15;

    float4 aR0 = *(const float4*)(arow0 + kv4);
    float4 aR1 = *(const float4*)(arow1 + kv4);
    float4 bR0 = *(const float4*)(W + (size_t)kb0 * GHID + n0 + nv4);
    float4 bR1 = *(const float4*)(W + (size_t)kb1 * GHID + n0 + nv4);

    for (int kt = 0; kt < DIN; kt += 16) {
        As[kv4 + 0][ra0] = aR0.x; As[kv4 + 1][ra0] = aR0.y;
        As[kv4 + 2][ra0] = aR0.z; As[kv4 + 3][ra0] = aR0.w;
        As[kv4 + 0][ra1] = aR1.x; As[kv4 + 1][ra1] = aR1.y;
        As[kv4 + 2][ra1] = aR1.z; As[kv4 + 3][ra1] = aR1.w;
        *(float4*)&Bs[kb0][nv4] = bR0;
        *(float4*)&Bs[kb1][nv4] = bR1;
        __syncthreads();

        if (kt + 16 < DIN) {
            aR0 = *(const float4*)(arow0 + kt + 16 + kv4);
            aR1 = *(const float4*)(arow1 + kt + 16 + kv4);
            bR0 = *(const float4*)(W + (size_t)(kt + 16 + kb0) * GHID + n0 + nv4);
            bR1 = *(const float4*)(W + (size_t)(kt + 16 + kb1) * GHID + n0 + nv4);
        }

#pragma unroll
        for (int kk = 0; kk < 16; kk++) {
            float a[8], b[8];
            *(float4*)&a[0] = *(const float4*)&As[kk][4 * ty];
            *(float4*)&a[4] = *(const float4*)&As[kk][64 + 4 * ty];
            *(float4*)&b[0] = *(const float4*)&Bs[kk][4 * tx];
            *(float4*)&b[4] = *(const float4*)&Bs[kk][64 + 4 * tx];
#pragma unroll
            for (int i = 0; i < 8; i++)
#pragma unroll
                for (int j = 0; j < 8; j++) acc[i][j] += a[i] * b[j];
        }
        __syncthreads();
    }

    float bn[8];
    {
        float4 b0 = *(const float4*)&bias[n0 + 4 * tx];
        float4 b1 = *(const float4*)&bias[n0 + 64 + 4 * tx];
        bn[0] = b0.x; bn[1] = b0.y; bn[2] = b0.z; bn[3] = b0.w;
        bn[4] = b1.x; bn[5] = b1.y; bn[6] = b1.z; bn[7] = b1.w;
    }

#pragma unroll
    for (int i = 0; i < 8; i++) {
        int m = m0 + ((i < 4) ? (4 * ty + i) : (64 + 4 * ty + (i - 4)));
        float* crow = g_g1 + (size_t)m * GHID;
        float4 v0, v1;
        v0.x = fmaxf(acc[i][0] + bn[0], 0.f); v0.y = fmaxf(acc[i][1] + bn[1], 0.f);
        v0.z = fmaxf(acc[i][2] + bn[2], 0.f); v0.w = fmaxf(acc[i][3] + bn[3], 0.f);
        v1.x = fmaxf(acc[i][4] + bn[4], 0.f); v1.y = fmaxf(acc[i][5] + bn[5], 0.f);
        v1.z = fmaxf(acc[i][6] + bn[6], 0.f); v1.w = fmaxf(acc[i][7] + bn[7], 0.f);
        *(float4*)&crow[n0 + 4 * tx]      = v0;
        *(float4*)&crow[n0 + 64 + 4 * tx] = v1;
    }
}

// =================================================================
// TF32 mma.sync grouped GEMM — R8 config (8 warps, 64x32 warp tile,
// 2 CTAs/SM) with BK=32 chunks: half the barriers per unit K, 2x
// global-load MLP. Loader runs in two half-chunks so only 16 loader
// regs are live (stays at the R8 register footprint). A smem [m][k]
// stride 36 (LDSM row-group stride 9 == 1 mod 8 -> conflict-free,
// rows 16B-aligned); B [k][n] stride 136. cvt.rna on the STS path —
// numerics byte-identical to the passing R8 build.
// MODE 1: H   = relu(x[tok] @ w1[e] + b1[e])           K=DIN
// MODE 2: MID = relu([H | x[tok]] @ [w2;wp] + b2+bp)   K=HID+DIN
// MODE 3: PO  = MID @ w3[e] + b3[e]                    K=HID
// =================================================================
#define MMA_TF32(d, a, b)                                                    \
    asm volatile(                                                            \
        "mma.sync.aligned.m16n8k8.row.col.f32.tf32.tf32.f32 "                \
        "{%0,%1,%2,%3}, {%4,%5,%6,%7}, {%8,%9}, {%0,%1,%2,%3};\n"            \
        : "+f"((d)[0]), "+f"((d)[1]), "+f"((d)[2]), "+f"((d)[3])             \
        : "r"((a)[0]), "r"((a)[1]), "r"((a)[2]), "r"((a)[3]),                \
          "r"((b)[0]), "r"((b)[1]))

#define LDSM_X4(r, addr)                                                     \
    asm volatile(                                                            \
        "ldmatrix.sync.aligned.m8n8.x4.shared.b16 {%0,%1,%2,%3}, [%4];\n"    \
        : "=r"((r)[0]), "=r"((r)[1]), "=r"((r)[2]), "=r"((r)[3])             \
        : "r"(addr))

#define A_ST 36              // A smem stride (floats) for 32-k rows
#define B_ST 136             // B smem stride (floats)
#define A_STG (128 * A_ST)   // 4608 floats per A stage
#define B_STG (32 * B_ST)    // 4352 floats per B stage
#define MMA_SMEM_FLOATS (2 * A_STG + 2 * B_STG)          // 17920
#define MMA_SMEM_BYTES  (MMA_SMEM_FLOATS * 4)            // 71680 B

template <int MODE, int KDIM, int NDIM, bool RELU>
__global__ void __launch_bounds__(256, 2) moe_mma_kernel(
    const float* __restrict__ x,
    const float* __restrict__ Wa,
    const float* __restrict__ Wb,
    const float* __restrict__ ba,
    const float* __restrict__ bb) {

    extern __shared__ __align__(16) unsigned smemU[];
    // layout: A stage0 [0,4608) A stage1 [4608,9216) B stage0 [9216,13568) B stage1 [13568,17920)

    const int e = (int)blockIdx.z;
    const int mcount = g_count[e];
    const int m0 = blockIdx.y * 128;
    if (m0 >= mcount) return;
    const int n0 = blockIdx.x * 128;
    const int tid  = threadIdx.x;
    const int lane = tid & 31;
    const int warp = tid >> 5;
    const int wm = (warp & 1) * 64;   // warp m-offset
    const int wn = (warp >> 1) * 32;  // warp n-offset
    const int group = lane >> 2;
    const int tl    = lane & 3;

    // ---- loader mapping (256 threads, 32-k chunks) ----
    // A: thread -> row ra = tid>>1, k-base kh = (tid&1)*16 (16 consecutive k)
    // B: thread -> rows kb + {0,8,16,24}, cols nv4..nv4+3
    const int ra = tid >> 1;
    const int kh = (tid & 1) * 16;
    const int kb = tid >> 5;           // 0..7
    const int nv4 = (tid & 31) * 4;

    // expert weight/bias pointers
    const float* W1e = Wa;
    const float* W2e = Wb;
    const float* b1e = ba;
    const float* b2e = bb;
    if (MODE == 1)      { W1e += (size_t)e * DIN * HID;  b1e += (size_t)e * HID; }
    else if (MODE == 2) { W1e += (size_t)e * HID * HID;  W2e += (size_t)e * DIN * HID;
                          b1e += (size_t)e * HID;        b2e += (size_t)e * HID; }
    else                { W1e += (size_t)e * HID * DOUT; b1e += (size_t)e * DOUT; }

    // A row base pointer (rows >= mcount read valid stale slots; never stored)
    const float* arow;
    const float* xrow = x;
    if (MODE == 1) {
        arow = x + (size_t)g_tok[e * CAP + m0 + ra] * DIN;
    } else if (MODE == 2) {
        xrow = x + (size_t)g_tok[e * CAP + m0 + ra] * DIN;
        arow = g_H + (size_t)(e * CAP + m0 + ra) * HID;
    } else {
        arow = g_MID + (size_t)(e * CAP + m0 + ra) * HID;
    }

    float4 aR[2], bR[2];
    // half hh of chunk at k-base kt: A k = kh + 8*hh + {0..7}; B rows kb+16*hh+{0,8}
    auto loadHalf = [&](int kt, int hh) {
        const float* asrc;
        const float* wsrc = W1e;
        int kloc = kt;
        if (MODE == 2 && kt >= HID) { asrc = xrow + (kt - HID); wsrc = W2e; kloc = kt - HID; }
        else                        { asrc = arow + kt; }
        asrc += kh + 8 * hh;
        aR[0] = *(const float4*)(asrc);
        aR[1] = *(const float4*)(asrc + 4);
        const float* bsrc = wsrc + (size_t)(kloc + kb + 16 * hh) * NDIM + n0 + nv4;
        bR[0] = *(const float4*)(bsrc);
        bR[1] = *(const float4*)(bsrc + (size_t)8 * NDIM);
    };
    auto storeHalf = [&](int s, int hh) {
        unsigned* Adst = smemU + s * A_STG + ra * A_ST + kh + 8 * hh;
        *(uint4*)(Adst)     = make_uint4(f2tf(aR[0].x), f2tf(aR[0].y), f2tf(aR[0].z), f2tf(aR[0].w));
        *(uint4*)(Adst + 4) = make_uint4(f2tf(aR[1].x), f2tf(aR[1].y), f2tf(aR[1].z), f2tf(aR[1].w));
        unsigned* Bdst = smemU + 2 * A_STG + s * B_STG + (kb + 16 * hh) * B_ST + nv4;
        *(uint4*)(Bdst)            = make_uint4(f2tf(bR[0].x), f2tf(bR[0].y), f2tf(bR[0].z), f2tf(bR[0].w));
        *(uint4*)(Bdst + 8 * B_ST) = make_uint4(f2tf(bR[1].x), f2tf(bR[1].y), f2tf(bR[1].z), f2tf(bR[1].w));
    };

    float acc[4][4][4];
#pragma unroll
    for (int mi = 0; mi < 4; mi++)
#pragma unroll
        for (int ni = 0; ni < 4; ni++)
#pragma unroll
            for (int r = 0; r < 4; r++) acc[mi][ni][r] = 0.f;

    // prologue: chunk 0 into stage 0
    loadHalf(0, 0); storeHalf(0, 0);
    loadHalf(0, 1); storeHalf(0, 1);
    __syncthreads();

    // LDSM base: row = wm + (lane & 15), k-offset = (lane >> 4) * 4 floats
    const unsigned aLdsmBase = (unsigned)__cvta_generic_to_shared(smemU)
        + (unsigned)(((wm + (lane & 15)) * A_ST + ((lane >> 4) << 2)) * 4);

    const int NCH = KDIM / 32;
#pragma unroll 1
    for (int c = 0; c < NCH; c++) {
        const unsigned aStage = aLdsmBase + (unsigned)((c & 1) * A_STG * 4);
        const unsigned* Bu = smemU + 2 * A_STG + (c & 1) * B_STG;
        const int more = (c + 1 < NCH);

        if (more) loadHalf((c + 1) * 32, 0);

#pragma unroll
        for (int ks = 0; ks < 16; ks += 8) {
            unsigned a[4][4], b[4][2];
#pragma unroll
            for (int mi = 0; mi < 4; mi++)
                LDSM_X4(a[mi], aStage + (unsigned)((mi * 16 * A_ST + ks) * 4));
#pragma unroll
            for (int ni = 0; ni < 4; ni++) {
                int nb = wn + ni * 8 + group;
                b[ni][0] = Bu[(ks + tl) * B_ST + nb];
                b[ni][1] = Bu[(ks + tl + 4) * B_ST + nb];
            }
#pragma unroll
            for (int mi = 0; mi < 4; mi++)
#pragma unroll
                for (int ni = 0; ni < 4; ni++)
                    MMA_TF32(acc[mi][ni], a[mi], b[ni]);
        }

        if (more) { storeHalf((c + 1) & 1, 0); loadHalf((c + 1) * 32, 1); }

#pragma unroll
        for (int ks = 16; ks < 32; ks += 8) {
            unsigned a[4][4], b[4][2];
#pragma unroll
            for (int mi = 0; mi < 4; mi++)
                LDSM_X4(a[mi], aStage + (unsigned)((mi * 16 * A_ST + ks) * 4));
#pragma unroll
            for (int ni = 0; ni < 4; ni++) {
                int nb = wn + ni * 8 + group;
                b[ni][0] = Bu[(ks + tl) * B_ST + nb];
                b[ni][1] = Bu[(ks + tl + 4) * B_ST + nb];
            }
#pragma unroll
            for (int mi = 0; mi < 4; mi++)
#pragma unroll
                for (int ni = 0; ni < 4; ni++)
                    MMA_TF32(acc[mi][ni], a[mi], b[ni]);
        }

        if (more) storeHalf((c + 1) & 1, 1);
        __syncthreads();
    }

    // ---- epilogue: per-column bias, optional relu, fragment store ----
    float2 bn[4];
#pragma unroll
    for (int ni = 0; ni < 4; ni++) {
        int col = n0 + wn + ni * 8 + tl * 2;
        bn[ni] = *(const float2*)&b1e[col];
        if (MODE == 2) {
            float2 c2 = *(const float2*)&b2e[col];
            bn[ni].x += c2.x; bn[ni].y += c2.y;
        }
    }

    float* Cb;
    if (MODE == 1)      Cb = g_H   + (size_t)e * CAP * NDIM;
    else if (MODE == 2) Cb = g_MID + (size_t)e * CAP * NDIM;
    else                Cb = g_PO  + (size_t)e * CAP * NDIM;

#pragma unroll
    for (int mi = 0; mi < 4; mi++) {
        int r0 = m0 + wm + mi * 16 + group;
        int r1 = r0 + 8;
        float* crow0 = Cb + (size_t)r0 * NDIM;
        float* crow1 = Cb + (size_t)r1 * NDIM;
#pragma unroll
        for (int ni = 0; ni < 4; ni++) {
            int col = n0 + wn + ni * 8 + tl * 2;
            float2 v0, v1;
            v0.x = acc[mi][ni][0] + bn[ni].x;
            v0.y = acc[mi][ni][1] + bn[ni].y;
            v1.x = acc[mi][ni][2] + bn[ni].x;
            v1.y = acc[mi][ni][3] + bn[ni].y;
            if (RELU) {
                v0.x = fmaxf(v0.x, 0.f); v0.y = fmaxf(v0.y, 0.f);
                v1.x = fmaxf(v1.x, 0.f); v1.y = fmaxf(v1.y, 0.f);
            }
            if (r0 < mcount) *(float2*)&crow0[col] = v0;
            if (r1 < mcount) *(float2*)&crow1[col] = v1;
        }
    }
}

// =================================================================
// Combine: out[t] = w0 * PO[p0] + w1 * PO[p1]  (deterministic)
// =================================================================
__global__ void combine_kernel(float* __restrict__ out) {
    const int t = blockIdx.x;
    const int p0 = g_pairpos[2 * t], p1 = g_pairpos[2 * t + 1];
    const float w0 = g_pairw[2 * t], w1 = g_pairw[2 * t + 1];
    const float4* r0 = (const float4*)(g_PO + (size_t)p0 * DOUT);
    const float4* r1 = (const float4*)(g_PO + (size_t)p1 * DOUT);
    float4* o = (float4*)(out + (size_t)t * DOUT);
    for (int c = threadIdx.x; c < DOUT / 4; c += blockDim.x) {
        float4 a = r0[c], b = r1[c], v;
        v.x = w0 * a.x + w1 * b.x;
        v.y = w0 * a.y + w1 * b.y;
        v.z = w0 * a.z + w1 * b.z;
        v.w = w0 * a.w + w1 * b.w;
        o[c] = v;
    }
}

// =================================================================
// Launch
// =================================================================
extern "C" void kernel_launch(void* const* d_in, const int* in_sizes, int n_in,
                              void* d_out, int out_size) {
    (void)in_sizes; (void)n_in; (void)out_size;
    const float* x   = (const float*)d_in[0];
    const float* w1  = (const float*)d_in[1];
    const float* b1  = (const float*)d_in[2];
    const float* w2  = (const float*)d_in[3];
    const float* b2  = (const float*)d_in[4];
    const float* w3  = (const float*)d_in[5];
    const float* b3  = (const float*)d_in[6];
    const float* wp  = (const float*)d_in[7];
    const float* bp  = (const float*)d_in[8];
    const float* gw1 = (const float*)d_in[9];
    const float* gb1 = (const float*)d_in[10];
    const float* gw2 = (const float*)d_in[11];
    const float* gb2 = (const float*)d_in[12];
    float* out = (float*)d_out;

    // opt-in to 70 KB dynamic smem (host-side, executes immediately; graph-safe)
    cudaFuncSetAttribute(moe_mma_kernel<1, DIN,       HID,  true>,
                         cudaFuncAttributeMaxDynamicSharedMemorySize, MMA_SMEM_BYTES);
    cudaFuncSetAttribute(moe_mma_kernel<2, HID + DIN, HID,  true>,
                         cudaFuncAttributeMaxDynamicSharedMemorySize, MMA_SMEM_BYTES);
    cudaFuncSetAttribute(moe_mma_kernel<3, HID,       DOUT, false>,
                         cudaFuncAttributeMaxDynamicSharedMemorySize, MMA_SMEM_BYTES);

    reset_counts_kernel<<<1, 32>>>();

    // Gating GEMM (exact fp32): g1 = relu(x @ gw1 + gb1)
    gating_gemm_kernel<<<dim3(GHID / 128, B_TOK / 128, 1), 256>>>(x, gw1, gb1);

    // Top-2 + softmax + scatter
    gating_topk_scatter_kernel<<<B_TOK, 128>>>(gw2, gb2);

    // GEMM1 (tf32): H = relu(x[tok] @ w1[e] + b1[e])
    moe_mma_kernel<1, DIN, HID, true>
        <<<dim3(HID / 128, CAP / 128, NEXP), 256, MMA_SMEM_BYTES>>>(
            x, w1, nullptr, b1, nullptr);

    // GEMM2 (tf32, fused wp): MID = relu([H | x] @ [w2; wp] + b2 + bp)
    moe_mma_kernel<2, HID + DIN, HID, true>
        <<<dim3(HID / 128, CAP / 128, NEXP), 256, MMA_SMEM_BYTES>>>(
            x, w2, wp, b2, bp);

    // GEMM3 (tf32): PO = MID @ w3[e] + b3[e]
    moe_mma_kernel<3, HID, DOUT, false>
        <<<dim3(DOUT / 128, CAP / 128, NEXP), 256, MMA_SMEM_BYTES>>>(
            x, w3, nullptr, b3, nullptr);

    // Weighted combine into output
    combine_kernel<<<B_TOK, 256>>>(out);
}

// round 14
// speedup vs baseline: 1.1893x; 1.0753x over previous
#include <cuda_runtime.h>
#include <math.h>

// Problem constants (match reference)
#define B_TOK 8192
#define DIN   1024
#define HID   2048
#define DOUT  1024
#define NEXP  8
#define GHID  1024
#define CAP   8192
#define KCAT  (HID + DIN)   // 3072

// -------- device scratch (static globals; allocation-free) --------
__device__ float g_g1[(size_t)B_TOK * GHID];           //  32 MB gating hidden
__device__ float g_H  [(size_t)NEXP * CAP * HID];      // 512 MB rnd(relu(x@w1+b1))
__device__ float g_MID[(size_t)NEXP * CAP * HID];      // 512 MB rnd(relu(...))
__device__ float g_PO [(size_t)NEXP * CAP * DOUT];     // 256 MB expert outputs (fp32)
__device__ float g_XR [(size_t)B_TOK * DIN];           //  32 MB rnd(x)
__device__ float g_W1R[(size_t)NEXP * DIN * HID];      //  64 MB rnd(w1)
__device__ float g_W2R[(size_t)NEXP * KCAT * HID];     // 192 MB rnd([w2;wp])
__device__ float g_W3R[(size_t)NEXP * HID * DOUT];     //  64 MB rnd(w3)
__device__ int   g_count[NEXP];
__device__ int   g_tok[NEXP * CAP];
__device__ int   g_pairpos[B_TOK * 2];
__device__ float g_pairw [B_TOK * 2];

__device__ __forceinline__ unsigned f2tf(float f) {
    unsigned u;
    asm("cvt.rna.tf32.f32 %0, %1;" : "=r"(u) : "f"(f));
    return u;
}
__device__ __forceinline__ float rndtf(float f) { return __uint_as_float(f2tf(f)); }

// =================================================================
// Reset per-expert counters (every replay)
// =================================================================
__global__ void reset_counts_kernel() {
    if (threadIdx.x < NEXP) g_count[threadIdx.x] = 0;
}

// =================================================================
// Pre-round operands to tf32 in gmem. Destination symbol is chosen
// INSIDE device code (host code must never take a __device__
// symbol's address — that was the R6 bug).
// =================================================================
template <int WHICH>   // 0 -> g_XR, 1 -> g_W1R, 3 -> g_W3R
__global__ void round_copy_kernel(const float* __restrict__ src, size_t n4) {
    float* dst = (WHICH == 0) ? g_XR : (WHICH == 1) ? g_W1R : g_W3R;
    size_t i = (size_t)blockIdx.x * blockDim.x + threadIdx.x;
    if (i >= n4) return;
    float4 v = ((const float4*)src)[i];
    v.x = rndtf(v.x); v.y = rndtf(v.y); v.z = rndtf(v.z); v.w = rndtf(v.w);
    ((float4*)dst)[i] = v;
}

// round + concatenate w2 / wp into g_W2R [e][KCAT][HID]
__global__ void round_w2cat_kernel(const float* __restrict__ w2,
                                   const float* __restrict__ wp) {
    const size_t P2 = (size_t)HID * HID / 4;
    const size_t Pp = (size_t)DIN * HID / 4;
    const size_t DSTE = (size_t)KCAT * HID / 4;
    size_t i = (size_t)blockIdx.x * blockDim.x + threadIdx.x;
    size_t total = (size_t)NEXP * (P2 + Pp);
    if (i >= total) return;
    size_t e = i / (P2 + Pp);
    size_t r = i % (P2 + Pp);
    float4 v; size_t dsti;
    if (r < P2) { v = ((const float4*)w2)[e * P2 + r];        dsti = e * DSTE + r; }
    else        { v = ((const float4*)wp)[e * Pp + (r - P2)]; dsti = e * DSTE + P2 + (r - P2); }
    v.x = rndtf(v.x); v.y = rndtf(v.y); v.z = rndtf(v.z); v.w = rndtf(v.w);
    ((float4*)g_W2R)[dsti] = v;
}

// =================================================================
// Gating epilogue: top-2 + softmax + scatter (exact fp32)
// =================================================================
__global__ void gating_topk_scatter_kernel(const float* __restrict__ gw2,
                                           const float* __restrict__ gb2) {
    const int t = blockIdx.x, tid = threadIdx.x;
    float acc[NEXP];
#pragma unroll
    for (int e = 0; e < NEXP; e++) acc[e] = 0.f;
    const float* row = g_g1 + (size_t)t * GHID;
    for (int k = tid; k < GHID; k += 128) {
        float v = row[k];
        const float* w = gw2 + (size_t)k * NEXP;
#pragma unroll
        for (int e = 0; e < NEXP; e++) acc[e] += v * w[e];
    }
    __shared__ float sm[128 * NEXP];
#pragma unroll
    for (int e = 0; e < NEXP; e++) sm[tid * NEXP + e] = acc[e];
    __syncthreads();
    for (int s = 64; s > 0; s >>= 1) {
        if (tid < s)
#pragma unroll
            for (int e = 0; e < NEXP; e++)
                sm[tid * NEXP + e] += sm[(tid + s) * NEXP + e];
        __syncthreads();
    }
    if (tid == 0) {
        float l[NEXP];
#pragma unroll
        for (int e = 0; e < NEXP; e++) l[e] = sm[e] + gb2[e];
        int i0 = 0;
#pragma unroll
        for (int e = 1; e < NEXP; e++) if (l[e] > l[i0]) i0 = e;
        int i1 = -1;
#pragma unroll
        for (int e = 0; e < NEXP; e++) {
            if (e == i0) continue;
            if (i1 < 0 || l[e] > l[i1]) i1 = e;
        }
        float r = expf(l[i1] - l[i0]);
        float w0 = 1.f / (1.f + r), w1 = r / (1.f + r);
        int p0 = atomicAdd(&g_count[i0], 1), s0 = i0 * CAP + p0;
        g_tok[s0] = t; g_pairpos[2 * t] = s0; g_pairw[2 * t] = w0;
        int p1 = atomicAdd(&g_count[i1], 1), s1 = i1 * CAP + p1;
        g_tok[s1] = t; g_pairpos[2 * t + 1] = s1; g_pairw[2 * t + 1] = w1;
    }
}

// =================================================================
// FP32 gating GEMM (exact): g1 = relu(x @ gw1 + gb1)
// =================================================================
__global__ void __launch_bounds__(256) gating_gemm_kernel(
    const float* __restrict__ x,
    const float* __restrict__ W,
    const float* __restrict__ bias) {

    __shared__ float As[16][128];
    __shared__ float Bs[16][128];

    const int m0 = blockIdx.y * 128;
    const int n0 = blockIdx.x * 128;
    const int tid = threadIdx.x;

    const int ra0 = tid >> 2;
    const int ra1 = 64 + ra0;
    const int kv4 = (tid & 3) * 4;
    const int kb0 = tid >> 5;
    const int kb1 = 8 + kb0;
    const int nv4 = (tid & 31) * 4;

    const float* arow0 = x + (size_t)(m0 + ra0) * DIN;
    const float* arow1 = x + (size_t)(m0 + ra1) * DIN;

    float acc[8][8];
#pragma unroll
    for (int i = 0; i < 8; i++)
#pragma unroll
        for (int j = 0; j < 8; j++) acc[i][j] = 0.f;

    const int ty = tid >> 4;
    const int tx = tid & 15;

    float4 aR0 = *(const float4*)(arow0 + kv4);
    float4 aR1 = *(const float4*)(arow1 + kv4);
    float4 bR0 = *(const float4*)(W + (size_t)kb0 * GHID + n0 + nv4);
    float4 bR1 = *(const float4*)(W + (size_t)kb1 * GHID + n0 + nv4);

    for (int kt = 0; kt < DIN; kt += 16) {
        As[kv4 + 0][ra0] = aR0.x; As[kv4 + 1][ra0] = aR0.y;
        As[kv4 + 2][ra0] = aR0.z; As[kv4 + 3][ra0] = aR0.w;
        As[kv4 + 0][ra1] = aR1.x; As[kv4 + 1][ra1] = aR1.y;
        As[kv4 + 2][ra1] = aR1.z; As[kv4 + 3][ra1] = aR1.w;
        *(float4*)&Bs[kb0][nv4] = bR0;
        *(float4*)&Bs[kb1][nv4] = bR1;
        __syncthreads();

        if (kt + 16 < DIN) {
            aR0 = *(const float4*)(arow0 + kt + 16 + kv4);
            aR1 = *(const float4*)(arow1 + kt + 16 + kv4);
            bR0 = *(const float4*)(W + (size_t)(kt + 16 + kb0) * GHID + n0 + nv4);
            bR1 = *(const float4*)(W + (size_t)(kt + 16 + kb1) * GHID + n0 + nv4);
        }

#pragma unroll
        for (int kk = 0; kk < 16; kk++) {
            float a[8], b[8];
            *(float4*)&a[0] = *(const float4*)&As[kk][4 * ty];
            *(float4*)&a[4] = *(const float4*)&As[kk][64 + 4 * ty];
            *(float4*)&b[0] = *(const float4*)&Bs[kk][4 * tx];
            *(float4*)&b[4] = *(const float4*)&Bs[kk][64 + 4 * tx];
#pragma unroll
            for (int i = 0; i < 8; i++)
#pragma unroll
                for (int j = 0; j < 8; j++) acc[i][j] += a[i] * b[j];
        }
        __syncthreads();
    }

    float bn[8];
    {
        float4 b0 = *(const float4*)&bias[n0 + 4 * tx];
        float4 b1 = *(const float4*)&bias[n0 + 64 + 4 * tx];
        bn[0] = b0.x; bn[1] = b0.y; bn[2] = b0.z; bn[3] = b0.w;
        bn[4] = b1.x; bn[5] = b1.y; bn[6] = b1.z; bn[7] = b1.w;
    }

#pragma unroll
    for (int i = 0; i < 8; i++) {
        int m = m0 + ((i < 4) ? (4 * ty + i) : (64 + 4 * ty + (i - 4)));
        float* crow = g_g1 + (size_t)m * GHID;
        float4 v0, v1;
        v0.x = fmaxf(acc[i][0] + bn[0], 0.f); v0.y = fmaxf(acc[i][1] + bn[1], 0.f);
        v0.z = fmaxf(acc[i][2] + bn[2], 0.f); v0.w = fmaxf(acc[i][3] + bn[3], 0.f);
        v1.x = fmaxf(acc[i][4] + bn[4], 0.f); v1.y = fmaxf(acc[i][5] + bn[5], 0.f);
        v1.z = fmaxf(acc[i][6] + bn[6], 0.f); v1.w = fmaxf(acc[i][7] + bn[7], 0.f);
        *(float4*)&crow[n0 + 4 * tx]      = v0;
        *(float4*)&crow[n0 + 64 + 4 * tx] = v1;
    }
}

// =================================================================
// TF32 mma.sync grouped GEMM — R8 tile config (8 warps, 64x32 warp
// tile, BK=16, 2 CTAs/SM) with a 4-stage cp.async pipeline. All
// gmem operands are PRE-ROUNDED tf32 (bitwise == R8's cvt-at-STS),
// so loads are raw 16B LDGSTS: no loader registers, no cvt, no STS.
// A smem [m][k] stride 20, B [k][n] stride 136 (fragment reads
// bank-verified, unchanged from R8). One commit per loop iteration
// keeps wait_group accounting exact.
// MODE 1: H   = rnd(relu(XR[tok] @ W1R + b1))      K=DIN
// MODE 2: MID = rnd(relu([H|XR] @ W2R + b2+bp))    K=KCAT
// MODE 3: PO  = MID @ W3R + b3                     K=HID
// =================================================================
#define MMA_TF32(d, a, b)                                                    \
    asm volatile(                                                            \
        "mma.sync.aligned.m16n8k8.row.col.f32.tf32.tf32.f32 "                \
        "{%0,%1,%2,%3}, {%4,%5,%6,%7}, {%8,%9}, {%0,%1,%2,%3};\n"            \
        : "+f"((d)[0]), "+f"((d)[1]), "+f"((d)[2]), "+f"((d)[3])             \
        : "r"((a)[0]), "r"((a)[1]), "r"((a)[2]), "r"((a)[3]),                \
          "r"((b)[0]), "r"((b)[1]))

#define LDSM_X4(r, addr)                                                     \
    asm volatile(                                                            \
        "ldmatrix.sync.aligned.m8n8.x4.shared.b16 {%0,%1,%2,%3}, [%4];\n"    \
        : "=r"((r)[0]), "=r"((r)[1]), "=r"((r)[2]), "=r"((r)[3])             \
        : "r"(addr))

#define CP_ASYNC16(saddr, gptr)                                              \
    asm volatile("cp.async.cg.shared.global [%0], [%1], 16;\n"               \
                 :: "r"(saddr), "l"(gptr) : "memory")
#define CP_COMMIT  asm volatile("cp.async.commit_group;\n" ::: "memory")
#define CP_WAIT2   asm volatile("cp.async.wait_group 2;\n" ::: "memory")

#define A_ST 20
#define B_ST 136
#define A_STG (128 * A_ST)                       // 2560 floats / stage
#define B_STG (16 * B_ST)                        // 2176 floats / stage
#define PIPE_SMEM_BYTES (4 * (A_STG + B_STG) * 4)   // 75776 B

template <int MODE, int KDIM, int NDIM, bool RELU, bool ROUND>
__global__ void __launch_bounds__(256, 2) moe_mma_async_kernel(
    const float* __restrict__ ba, const float* __restrict__ bb) {

    extern __shared__ __align__(16) float smem[];
    float* As = smem;                 // [4][128][A_ST]
    float* Bs = smem + 4 * A_STG;     // [4][16][B_ST]

    const int e = (int)blockIdx.z;
    const int mcount = g_count[e];
    const int m0 = blockIdx.y * 128;
    if (m0 >= mcount) return;
    const int n0 = blockIdx.x * 128;
    const int tid  = threadIdx.x;
    const int lane = tid & 31;
    const int warp = tid >> 5;
    const int wm = (warp & 1) * 64;
    const int wn = (warp >> 1) * 32;
    const int group = lane >> 2;
    const int tl    = lane & 3;

    // loader mapping (identical indices to R8)
    const int ra0 = tid >> 2;          // A rows ra0 and ra0+64
    const int kv4 = (tid & 3) * 4;
    const int kb0 = tid >> 5;          // B k-rows kb0 and kb0+8
    const int nv4 = (tid & 31) * 4;

    // pre-rounded weight base (internal symbols; concatenated for MODE 2)
    const float* W;
    if (MODE == 1)      W = g_W1R + (size_t)e * DIN * HID;
    else if (MODE == 2) W = g_W2R + (size_t)e * KCAT * HID;
    else                W = g_W3R + (size_t)e * HID * DOUT;

    const float* b1e = ba + (size_t)e * NDIM;
    const float* b2e = (MODE == 2) ? (bb + (size_t)e * NDIM) : (const float*)0;

    // A row base pointers (rows >= mcount read valid stale slots; never stored)
    const float *ar0, *ar1, *xr0 = 0, *xr1 = 0;
    if (MODE == 1) {
        ar0 = g_XR + (size_t)g_tok[e * CAP + m0 + ra0] * DIN;
        ar1 = g_XR + (size_t)g_tok[e * CAP + m0 + 64 + ra0] * DIN;
    } else if (MODE == 2) {
        ar0 = g_H + (size_t)(e * CAP + m0 + ra0) * HID;
        ar1 = g_H + (size_t)(e * CAP + m0 + 64 + ra0) * HID;
        xr0 = g_XR + (size_t)g_tok[e * CAP + m0 + ra0] * DIN;
        xr1 = g_XR + (size_t)g_tok[e * CAP + m0 + 64 + ra0] * DIN;
    } else {
        ar0 = g_MID + (size_t)(e * CAP + m0 + ra0) * HID;
        ar1 = g_MID + (size_t)(e * CAP + m0 + 64 + ra0) * HID;
    }

    const unsigned smemA = (unsigned)__cvta_generic_to_shared(As);
    const unsigned smemB = (unsigned)__cvta_generic_to_shared(Bs);

    auto issue_chunk = [&](int c) {
        const int kt = c * 16;
        const float *pa0, *pa1;
        if (MODE == 2 && kt >= HID) {
            pa0 = xr0 + (kt - HID) + kv4;
            pa1 = xr1 + (kt - HID) + kv4;
        } else {
            pa0 = ar0 + kt + kv4;
            pa1 = ar1 + kt + kv4;
        }
        unsigned sa = smemA + (unsigned)(((c & 3) * A_STG + ra0 * A_ST + kv4) * 4);
        CP_ASYNC16(sa, pa0);
        CP_ASYNC16(sa + 64 * A_ST * 4, pa1);
        const float* pb = W + (size_t)(kt + kb0) * NDIM + n0 + nv4;
        unsigned sb = smemB + (unsigned)(((c & 3) * B_STG + kb0 * B_ST + nv4) * 4);
        CP_ASYNC16(sb, pb);
        CP_ASYNC16(sb + 8 * B_ST * 4, pb + (size_t)8 * NDIM);
    };

    float acc[4][4][4];
#pragma unroll
    for (int mi = 0; mi < 4; mi++)
#pragma unroll
        for (int ni = 0; ni < 4; ni++)
#pragma unroll
            for (int r = 0; r < 4; r++) acc[mi][ni][r] = 0.f;

    const int NCH = KDIM / 16;
    issue_chunk(0); CP_COMMIT;
    issue_chunk(1); CP_COMMIT;
    issue_chunk(2); CP_COMMIT;

    // LDSM base: row = wm + (lane & 15), k-offset = (lane >> 4) * 4 floats
    const unsigned aLdsmBase = smemA
        + (unsigned)(((wm + (lane & 15)) * A_ST + ((lane >> 4) << 2)) * 4);
    const unsigned* BsU = (const unsigned*)Bs;

#pragma unroll 1
    for (int c = 0; c < NCH; c++) {
        CP_WAIT2;                    // chunk c resident (this thread)
        __syncthreads();             // all threads' chunk-c copies visible;
                                     // stage (c+3)&3 fully consumed (iter c-1)
        if (c + 3 < NCH) issue_chunk(c + 3);
        CP_COMMIT;                   // uniform group accounting

        const unsigned aStage = aLdsmBase + (unsigned)((c & 3) * A_STG * 4);
        const unsigned* Bu = BsU + (c & 3) * B_STG;
#pragma unroll
        for (int ks = 0; ks < 16; ks += 8) {
            unsigned a[4][4], b[4][2];
#pragma unroll
            for (int mi = 0; mi < 4; mi++)
                LDSM_X4(a[mi], aStage + (unsigned)((mi * 16 * A_ST + ks) * 4));
#pragma unroll
            for (int ni = 0; ni < 4; ni++) {
                int nb = wn + ni * 8 + group;
                b[ni][0] = Bu[(ks + tl) * B_ST + nb];
                b[ni][1] = Bu[(ks + tl + 4) * B_ST + nb];
            }
#pragma unroll
            for (int mi = 0; mi < 4; mi++)
#pragma unroll
                for (int ni = 0; ni < 4; ni++)
                    MMA_TF32(acc[mi][ni], a[mi], b[ni]);
        }
    }

    // ---- epilogue: per-column bias, optional relu/round, store ----
    float2 bn[4];
#pragma unroll
    for (int ni = 0; ni < 4; ni++) {
        int col = n0 + wn + ni * 8 + tl * 2;
        bn[ni] = *(const float2*)&b1e[col];
        if (MODE == 2) {
            float2 c2 = *(const float2*)&b2e[col];
            bn[ni].x += c2.x; bn[ni].y += c2.y;
        }
    }

    float* Cb;
    if (MODE == 1)      Cb = g_H   + (size_t)e * CAP * NDIM;
    else if (MODE == 2) Cb = g_MID + (size_t)e * CAP * NDIM;
    else                Cb = g_PO  + (size_t)e * CAP * NDIM;

#pragma unroll
    for (int mi = 0; mi < 4; mi++) {
        int r0 = m0 + wm + mi * 16 + group;
        int r1 = r0 + 8;
        float* crow0 = Cb + (size_t)r0 * NDIM;
        float* crow1 = Cb + (size_t)r1 * NDIM;
#pragma unroll
        for (int ni = 0; ni < 4; ni++) {
            int col = n0 + wn + ni * 8 + tl * 2;
            float2 v0, v1;
            v0.x = acc[mi][ni][0] + bn[ni].x;
            v0.y = acc[mi][ni][1] + bn[ni].y;
            v1.x = acc[mi][ni][2] + bn[ni].x;
            v1.y = acc[mi][ni][3] + bn[ni].y;
            if (RELU) {
                v0.x = fmaxf(v0.x, 0.f); v0.y = fmaxf(v0.y, 0.f);
                v1.x = fmaxf(v1.x, 0.f); v1.y = fmaxf(v1.y, 0.f);
            }
            if (ROUND) {   // consumed as a tf32 A operand by the next GEMM
                v0.x = __uint_as_float(f2tf(v0.x)); v0.y = __uint_as_float(f2tf(v0.y));
                v1.x = __uint_as_float(f2tf(v1.x)); v1.y = __uint_as_float(f2tf(v1.y));
            }
            if (r0 < mcount) *(float2*)&crow0[col] = v0;
            if (r1 < mcount) *(float2*)&crow1[col] = v1;
        }
    }
}

// =================================================================
// Combine: out[t] = w0 * PO[p0] + w1 * PO[p1]  (deterministic)
// =================================================================
__global__ void combine_kernel(float* __restrict__ out) {
    const int t = blockIdx.x;
    const int p0 = g_pairpos[2 * t], p1 = g_pairpos[2 * t + 1];
    const float w0 = g_pairw[2 * t], w1 = g_pairw[2 * t + 1];
    const float4* r0 = (const float4*)(g_PO + (size_t)p0 * DOUT);
    const float4* r1 = (const float4*)(g_PO + (size_t)p1 * DOUT);
    float4* o = (float4*)(out + (size_t)t * DOUT);
    for (int c = threadIdx.x; c < DOUT / 4; c += blockDim.x) {
        float4 a = r0[c], b = r1[c], v;
        v.x = w0 * a.x + w1 * b.x;
        v.y = w0 * a.y + w1 * b.y;
        v.z = w0 * a.z + w1 * b.z;
        v.w = w0 * a.w + w1 * b.w;
        o[c] = v;
    }
}

// =================================================================
// Launch
// =================================================================
extern "C" void kernel_launch(void* const* d_in, const int* in_sizes, int n_in,
                              void* d_out, int out_size) {
    (void)in_sizes; (void)n_in; (void)out_size;
    const float* x   = (const float*)d_in[0];
    const float* w1  = (const float*)d_in[1];
    const float* b1  = (const float*)d_in[2];
    const float* w2  = (const float*)d_in[3];
    const float* b2  = (const float*)d_in[4];
    const float* w3  = (const float*)d_in[5];
    const float* b3  = (const float*)d_in[6];
    const float* wp  = (const float*)d_in[7];
    const float* bp  = (const float*)d_in[8];
    const float* gw1 = (const float*)d_in[9];
    const float* gb1 = (const float*)d_in[10];
    const float* gw2 = (const float*)d_in[11];
    const float* gb2 = (const float*)d_in[12];
    float* out = (float*)d_out;

    // opt-in to 74 KB dynamic smem (host-side attribute; graph-safe)
    cudaFuncSetAttribute(moe_mma_async_kernel<1, DIN,  HID,  true,  true>,
                         cudaFuncAttributeMaxDynamicSharedMemorySize, PIPE_SMEM_BYTES);
    cudaFuncSetAttribute(moe_mma_async_kernel<2, KCAT, HID,  true,  true>,
                         cudaFuncAttributeMaxDynamicSharedMemorySize, PIPE_SMEM_BYTES);
    cudaFuncSetAttribute(moe_mma_async_kernel<3, HID,  DOUT, false, false>,
                         cudaFuncAttributeMaxDynamicSharedMemorySize, PIPE_SMEM_BYTES);

    reset_counts_kernel<<<1, 32>>>();

    // Pre-round operands (dst symbols resolved in device code)
    {
        size_t n4;
        n4 = (size_t)B_TOK * DIN / 4;
        round_copy_kernel<0><<<(unsigned)((n4 + 255) / 256), 256>>>(x, n4);
        n4 = (size_t)NEXP * DIN * HID / 4;
        round_copy_kernel<1><<<(unsigned)((n4 + 255) / 256), 256>>>(w1, n4);
        n4 = (size_t)NEXP * HID * DOUT / 4;
        round_copy_kernel<3><<<(unsigned)((n4 + 255) / 256), 256>>>(w3, n4);
        size_t nall = (size_t)NEXP * ((size_t)HID * HID / 4 + (size_t)DIN * HID / 4);
        round_w2cat_kernel<<<(unsigned)((nall + 255) / 256), 256>>>(w2, wp);
    }

    // Gating (exact fp32) + top-2 scatter
    gating_gemm_kernel<<<dim3(GHID / 128, B_TOK / 128, 1), 256>>>(x, gw1, gb1);
    gating_topk_scatter_kernel<<<B_TOK, 128>>>(gw2, gb2);

    // GEMM1: H = rnd(relu(XR[tok] @ W1R + b1))
    moe_mma_async_kernel<1, DIN, HID, true, true>
        <<<dim3(HID / 128, CAP / 128, NEXP), 256, PIPE_SMEM_BYTES>>>(b1, nullptr);

    // GEMM2 (fused wp): MID = rnd(relu([H|XR] @ W2R + b2 + bp))
    moe_mma_async_kernel<2, KCAT, HID, true, true>
        <<<dim3(HID / 128, CAP / 128, NEXP), 256, PIPE_SMEM_BYTES>>>(b2, bp);

    // GEMM3: PO = MID @ W3R + b3
    moe_mma_async_kernel<3, HID, DOUT, false, false>
        <<<dim3(DOUT / 128, CAP / 128, NEXP), 256, PIPE_SMEM_BYTES>>>(b3, nullptr);

    // Weighted combine into output
    combine_kernel<<<B_TOK, 256>>>(out);
}